// round 12
// baseline (speedup 1.0000x reference)
#include <cuda_runtime.h>
#include <cuda_fp16.h>
#include <cstdint>

#define F_IN 256
#define F_OUT 64
#define MAX_N 100000
#define MAX_E 3200000

// Scratch (device globals — no allocation allowed)
__device__ __half g_h16[(size_t)MAX_N * F_OUT];
__device__ float  g_s1[MAX_N];
__device__ float  g_s2[MAX_N];
__device__ int    g_deg[MAX_N];
__device__ int    g_rowptr[MAX_N + 1];
__device__ int    g_rank[MAX_E];
__device__ int    g_sdst[MAX_E];
__device__ int    g_bsum[128];
__device__ int    g_is64;

// ---------------------------------------------------------------------------
// init: detect edge dtype (block 0, warp 0) + zero deg (all blocks)
// ---------------------------------------------------------------------------
__global__ void init_kernel(const int* __restrict__ ei32, int M) {
    if (blockIdx.x == 0 && threadIdx.x < 32) {
        int lane = threadIdx.x;
        int bad = 0;
        for (int i = lane; i < 64; i += 32)
            if (ei32[2 * i + 1] != 0) bad = 1;
        unsigned m = __ballot_sync(0xffffffffu, bad);
        if (lane == 0) g_is64 = (m == 0u);
    }
    int i = blockIdx.x * blockDim.x + threadIdx.x;
    if (i < M) g_deg[i] = 0;
}

__device__ __forceinline__ int edge_at(const int* ei32, int is64, long long idx) {
    return is64 ? ei32[2 * idx] : ei32[idx];   // little-endian low word
}

// ---------------------------------------------------------------------------
// Packed f32x2 helpers (sm_100+ PTX; ptxas never auto-fuses FFMA2)
// ---------------------------------------------------------------------------
__device__ __forceinline__ unsigned long long pack_dup(float x) {
    unsigned long long r;
    unsigned u = __float_as_uint(x);
    asm("mov.b64 %0, {%1, %1};" : "=l"(r) : "r"(u));
    return r;
}
__device__ __forceinline__ void fma_f32x2(unsigned long long& acc,
                                          unsigned long long a,
                                          unsigned long long b) {
    asm("fma.rn.f32x2 %0, %1, %2, %0;" : "+l"(acc) : "l"(a), "l"(b));
}

// ---------------------------------------------------------------------------
// FUSED kernel: blocks [0, gemmBlocks) run the SGEMM (+s1/s2 epilogue);
// blocks [gemmBlocks, ...) run the edge-rank pass (histogram + rank).
// ---------------------------------------------------------------------------
__global__ __launch_bounds__(256) void gemm_rank_kernel(
    const float* __restrict__ X, const float* __restrict__ W,
    const float* __restrict__ a, const int* __restrict__ ei32,
    int M, int E, int gemmBlocks)
{
    __shared__ __align__(16) float Xs[32][132];
    __shared__ __align__(16) float Ws[32][64];

    if (blockIdx.x >= gemmBlocks) {
        // ---- rank path ----
        int e = (blockIdx.x - gemmBlocks) * 256 + threadIdx.x;
        if (e >= E) return;
        int is64 = g_is64;
        int src = edge_at(ei32, is64, e);
        int dst = edge_at(ei32, is64, (long long)E + e);
        int r = -1;
        if ((unsigned)src < (unsigned)M && (unsigned)dst < (unsigned)M)
            r = atomicAdd(&g_deg[src], 1);
        g_rank[e] = r;
        return;
    }

    // ---- gemm path ----
    int tid = threadIdx.x;
    int tx = tid & 15;   // col group: cols tx*4 .. tx*4+3
    int ty = tid >> 4;   // row group: rows ty*8 .. ty*8+7
    int m0 = blockIdx.x * 128;

    unsigned long long accp[4][4];
#pragma unroll
    for (int p = 0; p < 4; p++)
#pragma unroll
        for (int j = 0; j < 4; j++) accp[p][j] = 0ull;

    for (int k0 = 0; k0 < F_IN; k0 += 32) {
#pragma unroll
        for (int i = 0; i < 4; i++) {
            int idx = tid + i * 256;
            int r   = idx >> 3;
            int kc  = idx & 7;
            float4 v = make_float4(0.f, 0.f, 0.f, 0.f);
            int row = m0 + r;
            if (row < M)
                v = *(const float4*)(X + (size_t)row * F_IN + k0 + kc * 4);
            Xs[kc * 4 + 0][r] = v.x;
            Xs[kc * 4 + 1][r] = v.y;
            Xs[kc * 4 + 2][r] = v.z;
            Xs[kc * 4 + 3][r] = v.w;
        }
#pragma unroll
        for (int i = 0; i < 2; i++) {
            int idx = tid + i * 256;
            int kr  = idx >> 4;
            int c4  = idx & 15;
            float4 w = *(const float4*)(W + (size_t)(k0 + kr) * F_OUT + c4 * 4);
            *(float4*)&Ws[kr][c4 * 4] = w;
        }
        __syncthreads();

#pragma unroll
        for (int kk = 0; kk < 32; kk++) {
            float4 b = *(const float4*)&Ws[kk][tx * 4];
            unsigned long long bv0 = pack_dup(b.x);
            unsigned long long bv1 = pack_dup(b.y);
            unsigned long long bv2 = pack_dup(b.z);
            unsigned long long bv3 = pack_dup(b.w);
            unsigned long long av[4];
#pragma unroll
            for (int p = 0; p < 4; p++)
                av[p] = *(const unsigned long long*)&Xs[kk][ty * 8 + 2 * p];
#pragma unroll
            for (int p = 0; p < 4; p++) {
                fma_f32x2(accp[p][0], av[p], bv0);
                fma_f32x2(accp[p][1], av[p], bv1);
                fma_f32x2(accp[p][2], av[p], bv2);
                fma_f32x2(accp[p][3], av[p], bv3);
            }
        }
        __syncthreads();
    }

    float accf[8][4];
#pragma unroll
    for (int p = 0; p < 4; p++)
#pragma unroll
        for (int j = 0; j < 4; j++) {
            float2 f = *reinterpret_cast<float2*>(&accp[p][j]);
            accf[2 * p][j]     = f.x;
            accf[2 * p + 1][j] = f.y;
        }

    // Store h as fp16
#pragma unroll
    for (int i = 0; i < 8; i++) {
        int row = m0 + ty * 8 + i;
        if (row < M) {
            __half2 lo = __floats2half2_rn(accf[i][0], accf[i][1]);
            __half2 hi = __floats2half2_rn(accf[i][2], accf[i][3]);
            uint2 pkt = make_uint2(*(unsigned*)&lo, *(unsigned*)&hi);
            *(uint2*)(g_h16 + (size_t)row * F_OUT + tx * 4) = pkt;
        }
    }

    // Fused s1/s2 epilogue (fp32, exact)
    float a1v[4], a2v[4];
#pragma unroll
    for (int j = 0; j < 4; j++) {
        a1v[j] = __ldg(a + tx * 4 + j);
        a2v[j] = __ldg(a + 64 + tx * 4 + j);
    }
    float s1p[8], s2p[8];
#pragma unroll
    for (int i = 0; i < 8; i++) {
        float t1 = 0.f, t2 = 0.f;
#pragma unroll
        for (int j = 0; j < 4; j++) {
            t1 = fmaf(accf[i][j], a1v[j], t1);
            t2 = fmaf(accf[i][j], a2v[j], t2);
        }
        s1p[i] = t1; s2p[i] = t2;
    }
#pragma unroll
    for (int o = 1; o < 16; o <<= 1) {
#pragma unroll
        for (int i = 0; i < 8; i++) {
            s1p[i] += __shfl_xor_sync(0xffffffffu, s1p[i], o);
            s2p[i] += __shfl_xor_sync(0xffffffffu, s2p[i], o);
        }
    }
    if (tx == 0) {
#pragma unroll
        for (int i = 0; i < 8; i++) {
            int row = m0 + ty * 8 + i;
            if (row < M) { g_s1[row] = s1p[i]; g_s2[row] = s2p[i]; }
        }
    }
}

// ---------------------------------------------------------------------------
// Scan (rowptr from deg)
// ---------------------------------------------------------------------------
__global__ void scan1_kernel(int n) {
    __shared__ int s[1024];
    int i = blockIdx.x * 1024 + threadIdx.x;
    int v = (i < n) ? g_deg[i] : 0;
    s[threadIdx.x] = v;
    __syncthreads();
#pragma unroll
    for (int o = 1; o < 1024; o <<= 1) {
        int t = (threadIdx.x >= o) ? s[threadIdx.x - o] : 0;
        __syncthreads();
        s[threadIdx.x] += t;
        __syncthreads();
    }
    if (i < n) g_rowptr[i + 1] = s[threadIdx.x];
    if (threadIdx.x == 1023) g_bsum[blockIdx.x] = s[1023];
}

__global__ void scan2_kernel(int nb) {
    __shared__ int s[128];
    int v = (threadIdx.x < nb) ? g_bsum[threadIdx.x] : 0;
    s[threadIdx.x] = v;
    __syncthreads();
#pragma unroll
    for (int o = 1; o < 128; o <<= 1) {
        int t = (threadIdx.x >= o) ? s[threadIdx.x - o] : 0;
        __syncthreads();
        s[threadIdx.x] += t;
        __syncthreads();
    }
    if (threadIdx.x < nb) g_bsum[threadIdx.x] = s[threadIdx.x] - v;
}

__global__ void scan3_kernel(int n) {
    int i = blockIdx.x * blockDim.x + threadIdx.x;
    if (i < n) g_rowptr[i + 1] += g_bsum[i >> 10];
    if (i == 0) g_rowptr[0] = 0;
}

// ---------------------------------------------------------------------------
// Scatter: atomic-free using precomputed ranks
// ---------------------------------------------------------------------------
__global__ void scatter_kernel(const int* __restrict__ ei32, int E, int M) {
    int e = blockIdx.x * blockDim.x + threadIdx.x;
    if (e >= E) return;
    int r = g_rank[e];
    if (r < 0) return;
    int is64 = g_is64;
    int src = edge_at(ei32, is64, e);
    int dst = edge_at(ei32, is64, (long long)E + e);
    g_sdst[g_rowptr[src] + r] = dst;
}

// ---------------------------------------------------------------------------
// Aggregate + finalize: one warp per node, 8 edge-groups x 4 lanes,
// 16 feats/lane (two independent LDG.128 per edge per lane -> MLP 2x,
// serial depth deg/8). Prefetch next sdst. Fused rowsum-divide + ELU.
// w = exp(lrelu(s1[src]+s2[dst]))   (global-max subtraction cancels; skipped)
// ---------------------------------------------------------------------------
__global__ void aggregate_kernel(float* __restrict__ out, int M) {
    int node = (blockIdx.x * blockDim.x + threadIdx.x) >> 5;
    if (node >= M) return;
    int lane = threadIdx.x & 31;
    int sub  = lane & 3;    // feature block: feats sub*16 .. sub*16+15
    int eg   = lane >> 2;   // edge group 0..7

    int beg = g_rowptr[node];
    int end = g_rowptr[node + 1];
    float s1v = g_s1[node];

    float acc[16];
#pragma unroll
    for (int j = 0; j < 16; j++) acc[j] = 0.0f;
    float wsum = 0.0f;

    int p = beg + eg;
    int dst_cur = (p < end) ? g_sdst[p] : 0;
    for (; p < end; p += 8) {
        int pn = p + 8;
        int dst_next = (pn < end) ? g_sdst[pn] : 0;   // prefetch

        float s2v = g_s2[dst_cur];
        const __half* hb = g_h16 + (size_t)dst_cur * F_OUT + sub * 16;
        uint4 q0 = *(const uint4*)(hb);        // feats 0..7   (independent)
        uint4 q1 = *(const uint4*)(hb + 8);    // feats 8..15  (independent)

        float v  = s1v + s2v;
        float ev = v > 0.0f ? v : 0.2f * v;
        float w  = __expf(ev);
        wsum += w;

        float2 f0 = __half22float2(*(const __half2*)&q0.x);
        float2 f1 = __half22float2(*(const __half2*)&q0.y);
        float2 f2 = __half22float2(*(const __half2*)&q0.z);
        float2 f3 = __half22float2(*(const __half2*)&q0.w);
        float2 f4 = __half22float2(*(const __half2*)&q1.x);
        float2 f5 = __half22float2(*(const __half2*)&q1.y);
        float2 f6 = __half22float2(*(const __half2*)&q1.z);
        float2 f7 = __half22float2(*(const __half2*)&q1.w);
        acc[0]  = fmaf(w, f0.x, acc[0]);
        acc[1]  = fmaf(w, f0.y, acc[1]);
        acc[2]  = fmaf(w, f1.x, acc[2]);
        acc[3]  = fmaf(w, f1.y, acc[3]);
        acc[4]  = fmaf(w, f2.x, acc[4]);
        acc[5]  = fmaf(w, f2.y, acc[5]);
        acc[6]  = fmaf(w, f3.x, acc[6]);
        acc[7]  = fmaf(w, f3.y, acc[7]);
        acc[8]  = fmaf(w, f4.x, acc[8]);
        acc[9]  = fmaf(w, f4.y, acc[9]);
        acc[10] = fmaf(w, f5.x, acc[10]);
        acc[11] = fmaf(w, f5.y, acc[11]);
        acc[12] = fmaf(w, f6.x, acc[12]);
        acc[13] = fmaf(w, f6.y, acc[13]);
        acc[14] = fmaf(w, f7.x, acc[14]);
        acc[15] = fmaf(w, f7.y, acc[15]);

        dst_cur = dst_next;
    }

    // Reduce across the 8 edge groups (xor offsets 4, 8, 16 = group bits)
#pragma unroll
    for (int j = 0; j < 16; j++) {
        acc[j] += __shfl_xor_sync(0xffffffffu, acc[j], 4);
        acc[j] += __shfl_xor_sync(0xffffffffu, acc[j], 8);
        acc[j] += __shfl_xor_sync(0xffffffffu, acc[j], 16);
    }
    wsum += __shfl_xor_sync(0xffffffffu, wsum, 4);
    wsum += __shfl_xor_sync(0xffffffffu, wsum, 8);
    wsum += __shfl_xor_sync(0xffffffffu, wsum, 16);

    if (eg == 0) {
        float inv = 1.0f / (wsum + 1e-15f);
        float o[16];
#pragma unroll
        for (int j = 0; j < 16; j++) {
            float hp = acc[j] * inv;
            o[j] = hp > 0.0f ? hp : expm1f(hp);
        }
        float* dst = out + (size_t)node * F_OUT + sub * 16;
        *(float4*)(dst)      = make_float4(o[0],  o[1],  o[2],  o[3]);
        *(float4*)(dst + 4)  = make_float4(o[4],  o[5],  o[6],  o[7]);
        *(float4*)(dst + 8)  = make_float4(o[8],  o[9],  o[10], o[11]);
        *(float4*)(dst + 12) = make_float4(o[12], o[13], o[14], o[15]);
    }
}

// ---------------------------------------------------------------------------
extern "C" void kernel_launch(void* const* d_in, const int* in_sizes, int n_in,
                              void* d_out, int out_size) {
    // Identify inputs by element count (robust to metadata ordering)
    int idx[4] = {0, 1, 2, 3};
    for (int i = 1; i < 4 && i < n_in; i++) {
        int k = idx[i], j = i - 1;
        while (j >= 0 && in_sizes[idx[j]] < in_sizes[k]) { idx[j + 1] = idx[j]; j--; }
        idx[j + 1] = k;
    }
    const float* X    = (const float*)d_in[idx[0]];
    const int*   ei32 = (const int*)d_in[idx[1]];
    const float* W    = (const float*)d_in[idx[2]];
    const float* a    = (const float*)d_in[idx[3]];
    float*       out  = (float*)d_out;

    int M = in_sizes[idx[0]] / F_IN;   // 100000
    int E = in_sizes[idx[1]] / 2;      // 3200000

    init_kernel<<<(M + 511) / 512, 512>>>(ei32, M);

    int gemmBlocks = (M + 127) / 128;
    int rankBlocks = (E + 255) / 256;
    gemm_rank_kernel<<<gemmBlocks + rankBlocks, 256>>>(X, W, a, ei32, M, E, gemmBlocks);

    int nblk = (M + 1023) / 1024;
    scan1_kernel<<<nblk, 1024>>>(M);
    scan2_kernel<<<1, 128>>>(nblk);
    scan3_kernel<<<(M + 255) / 256, 256>>>(M);
    scatter_kernel<<<(E + 255) / 256, 256>>>(ei32, E, M);

    aggregate_kernel<<<(M * 32 + 255) / 256, 256>>>(out, M);
}

// round 14
// speedup vs baseline: 1.0315x; 1.0315x over previous
#include <cuda_runtime.h>
#include <cuda_fp16.h>
#include <cstdint>

#define F_IN 256
#define F_OUT 64
#define MAX_N 100000
#define MAX_E 3200000
#define KC 16                 // K-chunk staged in smem
#define XS_STRIDE 264         // floats per k-row of Xs (256 + 8 pad)

// Scratch (device globals — no allocation allowed)
__device__ __half g_h16[(size_t)MAX_N * F_OUT];
__device__ float  g_s1[MAX_N];
__device__ float  g_s2[MAX_N];
__device__ int    g_deg[MAX_N];
__device__ int    g_rowptr[MAX_N + 1];   // [i+1] = LOCAL inclusive scan of deg
__device__ int    g_rank[MAX_E];
__device__ int    g_sdst[MAX_E];
__device__ int    g_bsum[128];           // exclusive-scanned block sums
__device__ int    g_is64;

// rowbase(i): global exclusive prefix = local inclusive(i-1) + block offset
__device__ __forceinline__ int rowbase(int i) {
    return (i == 0) ? 0 : g_rowptr[i] + g_bsum[(i - 1) >> 10];
}

// ---------------------------------------------------------------------------
// init: detect edge dtype (block 0, warp 0) + zero deg (all blocks)
// ---------------------------------------------------------------------------
__global__ void init_kernel(const int* __restrict__ ei32, int M) {
    if (blockIdx.x == 0 && threadIdx.x < 32) {
        int lane = threadIdx.x;
        int bad = 0;
        for (int i = lane; i < 64; i += 32)
            if (ei32[2 * i + 1] != 0) bad = 1;
        unsigned m = __ballot_sync(0xffffffffu, bad);
        if (lane == 0) g_is64 = (m == 0u);
    }
    int i = blockIdx.x * blockDim.x + threadIdx.x;
    if (i < M) g_deg[i] = 0;
}

__device__ __forceinline__ int edge_at(const int* ei32, int is64, long long idx) {
    return is64 ? ei32[2 * idx] : ei32[idx];   // little-endian low word
}

// ---------------------------------------------------------------------------
// Packed f32x2 helpers (sm_100+ PTX; ptxas never auto-fuses FFMA2)
// ---------------------------------------------------------------------------
__device__ __forceinline__ unsigned long long pack_dup(float x) {
    unsigned long long r;
    unsigned u = __float_as_uint(x);
    asm("mov.b64 %0, {%1, %1};" : "=l"(r) : "r"(u));
    return r;
}
__device__ __forceinline__ void fma_f32x2(unsigned long long& acc,
                                          unsigned long long a,
                                          unsigned long long b) {
    asm("fma.rn.f32x2 %0, %1, %2, %0;" : "+l"(acc) : "l"(a), "l"(b));
}

// ---------------------------------------------------------------------------
// FUSED kernel: blocks [0, gemmBlocks) = 256x64 SGEMM (8x8 reg tile, f32x2,
// swizzled smem) + fused s1/s2 epilogue; blocks [gemmBlocks, ...) = rank pass.
// ---------------------------------------------------------------------------
__global__ __launch_bounds__(256) void gemm_rank_kernel(
    const float* __restrict__ X, const float* __restrict__ W,
    const float* __restrict__ a, const int* __restrict__ ei32,
    int M, int E, int gemmBlocks)
{
    __shared__ __align__(16) float Xs[KC][XS_STRIDE];
    __shared__ __align__(16) float Ws[KC][64];

    if (blockIdx.x >= gemmBlocks) {
        // ---- rank path ----
        int e = (blockIdx.x - gemmBlocks) * 256 + threadIdx.x;
        if (e >= E) return;
        int is64 = g_is64;
        int src = edge_at(ei32, is64, e);
        int dst = edge_at(ei32, is64, (long long)E + e);
        int r = -1;
        if ((unsigned)src < (unsigned)M && (unsigned)dst < (unsigned)M)
            r = atomicAdd(&g_deg[src], 1);
        g_rank[e] = r;
        return;
    }

    // ---- gemm path: 256 rows x 64 cols, thread tile 8x8 ----
    int tid = threadIdx.x;
    int tx = tid & 7;     // col group: cols tx*8 .. tx*8+7
    int ty = tid >> 3;    // row group: rows ty*8 .. ty*8+7 (0..31)
    int m0 = blockIdx.x * 256;

    unsigned long long accp[4][8];   // accp[p][j]: packed rows (2p,2p+1), col j
#pragma unroll
    for (int p = 0; p < 4; p++)
#pragma unroll
        for (int j = 0; j < 8; j++) accp[p][j] = 0ull;

    for (int k0 = 0; k0 < F_IN; k0 += KC) {
        // stage X chunk: 256 rows x KC, transposed + XOR-swizzled column
        // (store col = r ^ ((kc)<<2), kc = k>>2 -> conflict-free STS and LDS)
#pragma unroll
        for (int i = 0; i < (256 * KC / 4) / 256; i++) {   // KC=16 -> 4 iters
            int idx = tid + i * 256;
            int r   = idx >> 2;          // 0..255
            int kc  = idx & 3;           // float4 index within KC=16 slab
            float4 v = make_float4(0.f, 0.f, 0.f, 0.f);
            int row = m0 + r;
            if (row < M)
                v = *(const float4*)(X + (size_t)row * F_IN + k0 + kc * 4);
            int cs = r ^ (kc << 2);
            Xs[kc * 4 + 0][cs] = v.x;
            Xs[kc * 4 + 1][cs] = v.y;
            Xs[kc * 4 + 2][cs] = v.z;
            Xs[kc * 4 + 3][cs] = v.w;
        }
        // stage W chunk: KC x 64
        {
            int idx = tid;               // 256 float4 = KC*64/4
            int kr  = idx >> 4;
            int c4  = idx & 15;
            float4 w = *(const float4*)(W + (size_t)(k0 + kr) * F_OUT + c4 * 4);
            *(float4*)&Ws[kr][c4 * 4] = w;
        }
        __syncthreads();

#pragma unroll
        for (int kk = 0; kk < KC; kk++) {
            int swz = (kk >> 2) << 2;
            float4 b0 = *(const float4*)&Ws[kk][tx * 8];
            float4 b1 = *(const float4*)&Ws[kk][tx * 8 + 4];
            unsigned long long bv[8];
            bv[0] = pack_dup(b0.x); bv[1] = pack_dup(b0.y);
            bv[2] = pack_dup(b0.z); bv[3] = pack_dup(b0.w);
            bv[4] = pack_dup(b1.x); bv[5] = pack_dup(b1.y);
            bv[6] = pack_dup(b1.z); bv[7] = pack_dup(b1.w);
            unsigned long long av[4];
#pragma unroll
            for (int p = 0; p < 4; p++)
                av[p] = *(const unsigned long long*)&Xs[kk][(ty * 8 + 2 * p) ^ swz];
#pragma unroll
            for (int p = 0; p < 4; p++)
#pragma unroll
                for (int j = 0; j < 8; j++)
                    fma_f32x2(accp[p][j], av[p], bv[j]);
        }
        __syncthreads();
    }

    // Unpack: accf[i][j] = h[local row i][col tx*8+j]
    float accf[8][8];
#pragma unroll
    for (int p = 0; p < 4; p++)
#pragma unroll
        for (int j = 0; j < 8; j++) {
            float2 f = *reinterpret_cast<float2*>(&accp[p][j]);
            accf[2 * p][j]     = f.x;
            accf[2 * p + 1][j] = f.y;
        }

    // Store h as fp16: 8 cols -> 4 half2 -> one 16B store per row
#pragma unroll
    for (int i = 0; i < 8; i++) {
        int row = m0 + ty * 8 + i;
        if (row < M) {
            __half2 h0 = __floats2half2_rn(accf[i][0], accf[i][1]);
            __half2 h1 = __floats2half2_rn(accf[i][2], accf[i][3]);
            __half2 h2 = __floats2half2_rn(accf[i][4], accf[i][5]);
            __half2 h3 = __floats2half2_rn(accf[i][6], accf[i][7]);
            *(uint4*)(g_h16 + (size_t)row * F_OUT + tx * 8) =
                make_uint4(*(unsigned*)&h0, *(unsigned*)&h1,
                           *(unsigned*)&h2, *(unsigned*)&h3);
        }
    }

    // Fused s1/s2 epilogue (fp32, exact); reduce over the 8 tx lanes
    float a1v[8], a2v[8];
#pragma unroll
    for (int j = 0; j < 8; j++) {
        a1v[j] = __ldg(a + tx * 8 + j);
        a2v[j] = __ldg(a + 64 + tx * 8 + j);
    }
    float s1p[8], s2p[8];
#pragma unroll
    for (int i = 0; i < 8; i++) {
        float t1 = 0.f, t2 = 0.f;
#pragma unroll
        for (int j = 0; j < 8; j++) {
            t1 = fmaf(accf[i][j], a1v[j], t1);
            t2 = fmaf(accf[i][j], a2v[j], t2);
        }
        s1p[i] = t1; s2p[i] = t2;
    }
#pragma unroll
    for (int o = 1; o < 8; o <<= 1) {
#pragma unroll
        for (int i = 0; i < 8; i++) {
            s1p[i] += __shfl_xor_sync(0xffffffffu, s1p[i], o);
            s2p[i] += __shfl_xor_sync(0xffffffffu, s2p[i], o);
        }
    }
    if (tx == 0) {
#pragma unroll
        for (int i = 0; i < 8; i++) {
            int row = m0 + ty * 8 + i;
            if (row < M) { g_s1[row] = s1p[i]; g_s2[row] = s2p[i]; }
        }
    }
}

// ---------------------------------------------------------------------------
// Scan: scan1 = per-1024-block local inclusive; scan2 = exclusive block sums.
// (No scan3 — consumers use rowbase() inline.)
// ---------------------------------------------------------------------------
__global__ void scan1_kernel(int n) {
    __shared__ int s[1024];
    int i = blockIdx.x * 1024 + threadIdx.x;
    int v = (i < n) ? g_deg[i] : 0;
    s[threadIdx.x] = v;
    __syncthreads();
#pragma unroll
    for (int o = 1; o < 1024; o <<= 1) {
        int t = (threadIdx.x >= o) ? s[threadIdx.x - o] : 0;
        __syncthreads();
        s[threadIdx.x] += t;
        __syncthreads();
    }
    if (i < n) g_rowptr[i + 1] = s[threadIdx.x];
    if (threadIdx.x == 1023) g_bsum[blockIdx.x] = s[1023];
}

__global__ void scan2_kernel(int nb) {
    __shared__ int s[128];
    int v = (threadIdx.x < nb) ? g_bsum[threadIdx.x] : 0;
    s[threadIdx.x] = v;
    __syncthreads();
#pragma unroll
    for (int o = 1; o < 128; o <<= 1) {
        int t = (threadIdx.x >= o) ? s[threadIdx.x - o] : 0;
        __syncthreads();
        s[threadIdx.x] += t;
        __syncthreads();
    }
    if (threadIdx.x < nb) g_bsum[threadIdx.x] = s[threadIdx.x] - v;
}

// ---------------------------------------------------------------------------
// Scatter: atomic-free using precomputed ranks; rowptr via rowbase() inline
// ---------------------------------------------------------------------------
__global__ void scatter_kernel(const int* __restrict__ ei32, int E, int M) {
    int e = blockIdx.x * blockDim.x + threadIdx.x;
    if (e >= E) return;
    int r = g_rank[e];
    if (r < 0) return;
    int is64 = g_is64;
    int src = edge_at(ei32, is64, e);
    int dst = edge_at(ei32, is64, (long long)E + e);
    g_sdst[rowbase(src) + r] = dst;
}

// ---------------------------------------------------------------------------
// Aggregate + finalize (R7 form, frozen): one warp per node, 4 edge-groups x
// 8 lanes x 8 feats, prefetch next sdst. Fused rowsum-divide + ELU.
// w = exp(lrelu(s1[src]+s2[dst]))   (global-max subtraction cancels; skipped)
// ---------------------------------------------------------------------------
__global__ void aggregate_kernel(float* __restrict__ out, int M) {
    int node = (blockIdx.x * blockDim.x + threadIdx.x) >> 5;
    if (node >= M) return;
    int lane = threadIdx.x & 31;
    int sub  = lane & 7;
    int eg   = lane >> 3;

    int beg = rowbase(node);
    int end = rowbase(node + 1);
    float s1v = g_s1[node];

    float acc[8];
#pragma unroll
    for (int j = 0; j < 8; j++) acc[j] = 0.0f;
    float wsum = 0.0f;

    int p = beg + eg;
    int dst_cur = (p < end) ? g_sdst[p] : 0;
    for (; p < end; p += 4) {
        int pn = p + 4;
        int dst_next = (pn < end) ? g_sdst[pn] : 0;   // prefetch

        float s2v = g_s2[dst_cur];
        uint4 q = *(const uint4*)(g_h16 + (size_t)dst_cur * F_OUT + sub * 8);

        float v  = s1v + s2v;
        float ev = v > 0.0f ? v : 0.2f * v;
        float w  = __expf(ev);
        wsum += w;

        float2 f0 = __half22float2(*(const __half2*)&q.x);
        float2 f1 = __half22float2(*(const __half2*)&q.y);
        float2 f2 = __half22float2(*(const __half2*)&q.z);
        float2 f3 = __half22float2(*(const __half2*)&q.w);
        acc[0] = fmaf(w, f0.x, acc[0]);
        acc[1] = fmaf(w, f0.y, acc[1]);
        acc[2] = fmaf(w, f1.x, acc[2]);
        acc[3] = fmaf(w, f1.y, acc[3]);
        acc[4] = fmaf(w, f2.x, acc[4]);
        acc[5] = fmaf(w, f2.y, acc[5]);
        acc[6] = fmaf(w, f3.x, acc[6]);
        acc[7] = fmaf(w, f3.y, acc[7]);

        dst_cur = dst_next;
    }

#pragma unroll
    for (int j = 0; j < 8; j++) {
        acc[j] += __shfl_xor_sync(0xffffffffu, acc[j], 8);
        acc[j] += __shfl_xor_sync(0xffffffffu, acc[j], 16);
    }
    wsum += __shfl_xor_sync(0xffffffffu, wsum, 8);
    wsum += __shfl_xor_sync(0xffffffffu, wsum, 16);

    if (eg == 0) {
        float inv = 1.0f / (wsum + 1e-15f);
        float o[8];
#pragma unroll
        for (int j = 0; j < 8; j++) {
            float hp = acc[j] * inv;
            o[j] = hp > 0.0f ? hp : expm1f(hp);
        }
        float* dst = out + (size_t)node * F_OUT + sub * 8;
        *(float4*)(dst)     = make_float4(o[0], o[1], o[2], o[3]);
        *(float4*)(dst + 4) = make_float4(o[4], o[5], o[6], o[7]);
    }
}

// ---------------------------------------------------------------------------
extern "C" void kernel_launch(void* const* d_in, const int* in_sizes, int n_in,
                              void* d_out, int out_size) {
    // Identify inputs by element count (robust to metadata ordering)
    int idx[4] = {0, 1, 2, 3};
    for (int i = 1; i < 4 && i < n_in; i++) {
        int k = idx[i], j = i - 1;
        while (j >= 0 && in_sizes[idx[j]] < in_sizes[k]) { idx[j + 1] = idx[j]; j--; }
        idx[j + 1] = k;
    }
    const float* X    = (const float*)d_in[idx[0]];
    const int*   ei32 = (const int*)d_in[idx[1]];
    const float* W    = (const float*)d_in[idx[2]];
    const float* a    = (const float*)d_in[idx[3]];
    float*       out  = (float*)d_out;

    int M = in_sizes[idx[0]] / F_IN;   // 100000
    int E = in_sizes[idx[1]] / 2;      // 3200000

    init_kernel<<<(M + 511) / 512, 512>>>(ei32, M);

    int gemmBlocks = (M + 255) / 256;
    int rankBlocks = (E + 255) / 256;
    gemm_rank_kernel<<<gemmBlocks + rankBlocks, 256>>>(X, W, a, ei32, M, E, gemmBlocks);

    int nblk = (M + 1023) / 1024;
    scan1_kernel<<<nblk, 1024>>>(M);
    scan2_kernel<<<1, 128>>>(nblk);
    scatter_kernel<<<(E + 255) / 256, 256>>>(ei32, E, M);

    aggregate_kernel<<<(M * 32 + 255) / 256, 256>>>(out, M);
}

// round 15
// speedup vs baseline: 1.1208x; 1.0865x over previous
#include <cuda_runtime.h>
#include <cuda_fp16.h>
#include <cstdint>

#define F_IN 256
#define F_OUT 64
#define MAX_N 100000
#define MAX_E 3200000

// Scratch (device globals — no allocation allowed)
__device__ __half g_h16[(size_t)MAX_N * F_OUT];
__device__ float  g_s1[MAX_N];
__device__ float  g_s2[MAX_N];
__device__ int    g_deg[MAX_N];
__device__ int    g_rowptr[MAX_N + 1];   // [i+1] = LOCAL inclusive scan of deg
__device__ int    g_rank[MAX_E];
__device__ int    g_sdst[MAX_E];
__device__ int    g_bsum[128];           // exclusive-scanned block sums
__device__ int    g_scan_ctr;
__device__ int    g_is64;

// rowbase(i): global exclusive prefix = local inclusive(i-1) + block offset
__device__ __forceinline__ int rowbase(int i) {
    return (i == 0) ? 0 : g_rowptr[i] + g_bsum[(i - 1) >> 10];
}

// ---------------------------------------------------------------------------
// init: detect edge dtype (block 0 warp 0), zero deg, zero scan counter
// ---------------------------------------------------------------------------
__global__ void init_kernel(const int* __restrict__ ei32, int M) {
    if (blockIdx.x == 0 && threadIdx.x < 32) {
        int lane = threadIdx.x;
        int bad = 0;
        for (int i = lane; i < 64; i += 32)
            if (ei32[2 * i + 1] != 0) bad = 1;
        unsigned m = __ballot_sync(0xffffffffu, bad);
        if (lane == 0) { g_is64 = (m == 0u); g_scan_ctr = 0; }
    }
    int i = blockIdx.x * blockDim.x + threadIdx.x;
    if (i < M) g_deg[i] = 0;
}

__device__ __forceinline__ int edge_at(const int* ei32, int is64, long long idx) {
    return is64 ? ei32[2 * idx] : ei32[idx];   // little-endian low word
}

// ---------------------------------------------------------------------------
// Packed f32x2 helpers (sm_100+ PTX; ptxas never auto-fuses FFMA2)
// ---------------------------------------------------------------------------
__device__ __forceinline__ unsigned long long pack_dup(float x) {
    unsigned long long r;
    unsigned u = __float_as_uint(x);
    asm("mov.b64 %0, {%1, %1};" : "=l"(r) : "r"(u));
    return r;
}
__device__ __forceinline__ void fma_f32x2(unsigned long long& acc,
                                          unsigned long long a,
                                          unsigned long long b) {
    asm("fma.rn.f32x2 %0, %1, %2, %0;" : "+l"(acc) : "l"(a), "l"(b));
}

// ---------------------------------------------------------------------------
// FUSED kernel (R7 form, frozen): blocks [0, gemmBlocks) = 128x64 SGEMM
// (f32x2, 8x4 thread tile) + fused s1/s2 epilogue; rest = rank pass.
// ---------------------------------------------------------------------------
__global__ __launch_bounds__(256) void gemm_rank_kernel(
    const float* __restrict__ X, const float* __restrict__ W,
    const float* __restrict__ a, const int* __restrict__ ei32,
    int M, int E, int gemmBlocks)
{
    __shared__ __align__(16) float Xs[32][132];
    __shared__ __align__(16) float Ws[32][64];

    if (blockIdx.x >= gemmBlocks) {
        // ---- rank path ----
        int e = (blockIdx.x - gemmBlocks) * 256 + threadIdx.x;
        if (e >= E) return;
        int is64 = g_is64;
        int src = edge_at(ei32, is64, e);
        int dst = edge_at(ei32, is64, (long long)E + e);
        int r = -1;
        if ((unsigned)src < (unsigned)M && (unsigned)dst < (unsigned)M)
            r = atomicAdd(&g_deg[src], 1);
        g_rank[e] = r;
        return;
    }

    // ---- gemm path ----
    int tid = threadIdx.x;
    int tx = tid & 15;   // col group: cols tx*4 .. tx*4+3
    int ty = tid >> 4;   // row group: rows ty*8 .. ty*8+7
    int m0 = blockIdx.x * 128;

    unsigned long long accp[4][4];
#pragma unroll
    for (int p = 0; p < 4; p++)
#pragma unroll
        for (int j = 0; j < 4; j++) accp[p][j] = 0ull;

    for (int k0 = 0; k0 < F_IN; k0 += 32) {
#pragma unroll
        for (int i = 0; i < 4; i++) {
            int idx = tid + i * 256;
            int r   = idx >> 3;
            int kc  = idx & 7;
            float4 v = make_float4(0.f, 0.f, 0.f, 0.f);
            int row = m0 + r;
            if (row < M)
                v = *(const float4*)(X + (size_t)row * F_IN + k0 + kc * 4);
            Xs[kc * 4 + 0][r] = v.x;
            Xs[kc * 4 + 1][r] = v.y;
            Xs[kc * 4 + 2][r] = v.z;
            Xs[kc * 4 + 3][r] = v.w;
        }
#pragma unroll
        for (int i = 0; i < 2; i++) {
            int idx = tid + i * 256;
            int kr  = idx >> 4;
            int c4  = idx & 15;
            float4 w = *(const float4*)(W + (size_t)(k0 + kr) * F_OUT + c4 * 4);
            *(float4*)&Ws[kr][c4 * 4] = w;
        }
        __syncthreads();

#pragma unroll
        for (int kk = 0; kk < 32; kk++) {
            float4 b = *(const float4*)&Ws[kk][tx * 4];
            unsigned long long bv0 = pack_dup(b.x);
            unsigned long long bv1 = pack_dup(b.y);
            unsigned long long bv2 = pack_dup(b.z);
            unsigned long long bv3 = pack_dup(b.w);
            unsigned long long av[4];
#pragma unroll
            for (int p = 0; p < 4; p++)
                av[p] = *(const unsigned long long*)&Xs[kk][ty * 8 + 2 * p];
#pragma unroll
            for (int p = 0; p < 4; p++) {
                fma_f32x2(accp[p][0], av[p], bv0);
                fma_f32x2(accp[p][1], av[p], bv1);
                fma_f32x2(accp[p][2], av[p], bv2);
                fma_f32x2(accp[p][3], av[p], bv3);
            }
        }
        __syncthreads();
    }

    float accf[8][4];
#pragma unroll
    for (int p = 0; p < 4; p++)
#pragma unroll
        for (int j = 0; j < 4; j++) {
            float2 f = *reinterpret_cast<float2*>(&accp[p][j]);
            accf[2 * p][j]     = f.x;
            accf[2 * p + 1][j] = f.y;
        }

    // Store h as fp16
#pragma unroll
    for (int i = 0; i < 8; i++) {
        int row = m0 + ty * 8 + i;
        if (row < M) {
            __half2 lo = __floats2half2_rn(accf[i][0], accf[i][1]);
            __half2 hi = __floats2half2_rn(accf[i][2], accf[i][3]);
            uint2 pkt = make_uint2(*(unsigned*)&lo, *(unsigned*)&hi);
            *(uint2*)(g_h16 + (size_t)row * F_OUT + tx * 4) = pkt;
        }
    }

    // Fused s1/s2 epilogue (fp32, exact)
    float a1v[4], a2v[4];
#pragma unroll
    for (int j = 0; j < 4; j++) {
        a1v[j] = __ldg(a + tx * 4 + j);
        a2v[j] = __ldg(a + 64 + tx * 4 + j);
    }
    float s1p[8], s2p[8];
#pragma unroll
    for (int i = 0; i < 8; i++) {
        float t1 = 0.f, t2 = 0.f;
#pragma unroll
        for (int j = 0; j < 4; j++) {
            t1 = fmaf(accf[i][j], a1v[j], t1);
            t2 = fmaf(accf[i][j], a2v[j], t2);
        }
        s1p[i] = t1; s2p[i] = t2;
    }
#pragma unroll
    for (int o = 1; o < 16; o <<= 1) {
#pragma unroll
        for (int i = 0; i < 8; i++) {
            s1p[i] += __shfl_xor_sync(0xffffffffu, s1p[i], o);
            s2p[i] += __shfl_xor_sync(0xffffffffu, s2p[i], o);
        }
    }
    if (tx == 0) {
#pragma unroll
        for (int i = 0; i < 8; i++) {
            int row = m0 + ty * 8 + i;
            if (row < M) { g_s1[row] = s1p[i]; g_s2[row] = s2p[i]; }
        }
    }
}

// ---------------------------------------------------------------------------
// Fused scan: per-1024-block local inclusive scan; the LAST block to finish
// also exclusive-scans the (<=128) block sums in place (threadfence+counter).
// ---------------------------------------------------------------------------
__global__ void scan_kernel(int n, int nblk) {
    __shared__ int s[1024];
    __shared__ int isLast;
    int i = blockIdx.x * 1024 + threadIdx.x;
    int v = (i < n) ? g_deg[i] : 0;
    s[threadIdx.x] = v;
    __syncthreads();
#pragma unroll
    for (int o = 1; o < 1024; o <<= 1) {
        int t = (threadIdx.x >= o) ? s[threadIdx.x - o] : 0;
        __syncthreads();
        s[threadIdx.x] += t;
        __syncthreads();
    }
    if (i < n) g_rowptr[i + 1] = s[threadIdx.x];
    if (threadIdx.x == 1023) {
        g_bsum[blockIdx.x] = s[1023];
        __threadfence();
        int prev = atomicAdd(&g_scan_ctr, 1);
        isLast = (prev == nblk - 1);
    }
    __syncthreads();
    if (isLast) {
        __threadfence();   // acquire all blocks' bsum writes
        int bv = (threadIdx.x < nblk) ? g_bsum[threadIdx.x] : 0;
        if (threadIdx.x < 128) s[threadIdx.x] = bv;
        __syncthreads();
#pragma unroll
        for (int o = 1; o < 128; o <<= 1) {
            int t = (threadIdx.x < 128 && threadIdx.x >= o) ? s[threadIdx.x - o] : 0;
            __syncthreads();
            if (threadIdx.x < 128) s[threadIdx.x] += t;
            __syncthreads();
        }
        if (threadIdx.x < nblk) g_bsum[threadIdx.x] = s[threadIdx.x] - bv;
    }
}

// ---------------------------------------------------------------------------
// Scatter: atomic-free using precomputed ranks; rowptr via rowbase() inline
// ---------------------------------------------------------------------------
__global__ void scatter_kernel(const int* __restrict__ ei32, int E, int M) {
    int e = blockIdx.x * blockDim.x + threadIdx.x;
    if (e >= E) return;
    int r = g_rank[e];
    if (r < 0) return;
    int is64 = g_is64;
    int src = edge_at(ei32, is64, e);
    int dst = edge_at(ei32, is64, (long long)E + e);
    g_sdst[rowbase(src) + r] = dst;
}

// ---------------------------------------------------------------------------
// Aggregate + finalize (R7 form, frozen): one warp per node, 4 edge-groups x
// 8 lanes x 8 feats, prefetch next sdst. Fused rowsum-divide + ELU.
// w = exp(lrelu(s1[src]+s2[dst]))   (global-max subtraction cancels; skipped)
// ---------------------------------------------------------------------------
__global__ void aggregate_kernel(float* __restrict__ out, int M) {
    int node = (blockIdx.x * blockDim.x + threadIdx.x) >> 5;
    if (node >= M) return;
    int lane = threadIdx.x & 31;
    int sub  = lane & 7;
    int eg   = lane >> 3;

    int beg = rowbase(node);
    int end = rowbase(node + 1);
    float s1v = g_s1[node];

    float acc[8];
#pragma unroll
    for (int j = 0; j < 8; j++) acc[j] = 0.0f;
    float wsum = 0.0f;

    int p = beg + eg;
    int dst_cur = (p < end) ? g_sdst[p] : 0;
    for (; p < end; p += 4) {
        int pn = p + 4;
        int dst_next = (pn < end) ? g_sdst[pn] : 0;   // prefetch

        float s2v = g_s2[dst_cur];
        uint4 q = *(const uint4*)(g_h16 + (size_t)dst_cur * F_OUT + sub * 8);

        float v  = s1v + s2v;
        float ev = v > 0.0f ? v : 0.2f * v;
        float w  = __expf(ev);
        wsum += w;

        float2 f0 = __half22float2(*(const __half2*)&q.x);
        float2 f1 = __half22float2(*(const __half2*)&q.y);
        float2 f2 = __half22float2(*(const __half2*)&q.z);
        float2 f3 = __half22float2(*(const __half2*)&q.w);
        acc[0] = fmaf(w, f0.x, acc[0]);
        acc[1] = fmaf(w, f0.y, acc[1]);
        acc[2] = fmaf(w, f1.x, acc[2]);
        acc[3] = fmaf(w, f1.y, acc[3]);
        acc[4] = fmaf(w, f2.x, acc[4]);
        acc[5] = fmaf(w, f2.y, acc[5]);
        acc[6] = fmaf(w, f3.x, acc[6]);
        acc[7] = fmaf(w, f3.y, acc[7]);

        dst_cur = dst_next;
    }

#pragma unroll
    for (int j = 0; j < 8; j++) {
        acc[j] += __shfl_xor_sync(0xffffffffu, acc[j], 8);
        acc[j] += __shfl_xor_sync(0xffffffffu, acc[j], 16);
    }
    wsum += __shfl_xor_sync(0xffffffffu, wsum, 8);
    wsum += __shfl_xor_sync(0xffffffffu, wsum, 16);

    if (eg == 0) {
        float inv = 1.0f / (wsum + 1e-15f);
        float o[8];
#pragma unroll
        for (int j = 0; j < 8; j++) {
            float hp = acc[j] * inv;
            o[j] = hp > 0.0f ? hp : expm1f(hp);
        }
        float* dst = out + (size_t)node * F_OUT + sub * 8;
        *(float4*)(dst)     = make_float4(o[0], o[1], o[2], o[3]);
        *(float4*)(dst + 4) = make_float4(o[4], o[5], o[6], o[7]);
    }
}

// ---------------------------------------------------------------------------
extern "C" void kernel_launch(void* const* d_in, const int* in_sizes, int n_in,
                              void* d_out, int out_size) {
    // Identify inputs by element count (robust to metadata ordering)
    int idx[4] = {0, 1, 2, 3};
    for (int i = 1; i < 4 && i < n_in; i++) {
        int k = idx[i], j = i - 1;
        while (j >= 0 && in_sizes[idx[j]] < in_sizes[k]) { idx[j + 1] = idx[j]; j--; }
        idx[j + 1] = k;
    }
    const float* X    = (const float*)d_in[idx[0]];
    const int*   ei32 = (const int*)d_in[idx[1]];
    const float* W    = (const float*)d_in[idx[2]];
    const float* a    = (const float*)d_in[idx[3]];
    float*       out  = (float*)d_out;

    int M = in_sizes[idx[0]] / F_IN;   // 100000
    int E = in_sizes[idx[1]] / 2;      // 3200000

    init_kernel<<<(M + 511) / 512, 512>>>(ei32, M);

    int gemmBlocks = (M + 127) / 128;
    int rankBlocks = (E + 255) / 256;
    gemm_rank_kernel<<<gemmBlocks + rankBlocks, 256>>>(X, W, a, ei32, M, E, gemmBlocks);

    int nblk = (M + 1023) / 1024;
    scan_kernel<<<nblk, 1024>>>(M, nblk);
    scatter_kernel<<<(E + 255) / 256, 256>>>(ei32, E, M);

    aggregate_kernel<<<(M * 32 + 255) / 256, 256>>>(out, M);
}

// round 16
// speedup vs baseline: 1.1743x; 1.0478x over previous
#include <cuda_runtime.h>
#include <cuda_fp16.h>
#include <cstdint>

#define F_IN 256
#define F_OUT 64
#define MAX_N 100000
#define MAX_E 3200000

// Scratch (device globals — no allocation allowed)
__device__ __half g_h16[(size_t)MAX_N * F_OUT];
__device__ float  g_s1[MAX_N];
__device__ float  g_s2[MAX_N];
__device__ int    g_deg[MAX_N];
__device__ int    g_rowptr[MAX_N + 1];   // [i+1] = LOCAL inclusive scan of deg
__device__ int    g_rank[MAX_E];
__device__ int    g_sdst[MAX_E];
__device__ int    g_bsum[128];           // exclusive-scanned block sums
__device__ int    g_scan_ctr;
__device__ int    g_is64;

// rowbase(i): global exclusive prefix = local inclusive(i-1) + block offset
__device__ __forceinline__ int rowbase(int i) {
    return (i == 0) ? 0 : g_rowptr[i] + g_bsum[(i - 1) >> 10];
}

// ---------------------------------------------------------------------------
// init: detect edge dtype (block 0 warp 0), zero deg, zero scan counter
// ---------------------------------------------------------------------------
__global__ void init_kernel(const int* __restrict__ ei32, int M) {
    if (blockIdx.x == 0 && threadIdx.x < 32) {
        int lane = threadIdx.x;
        int bad = 0;
        for (int i = lane; i < 64; i += 32)
            if (ei32[2 * i + 1] != 0) bad = 1;
        unsigned m = __ballot_sync(0xffffffffu, bad);
        if (lane == 0) { g_is64 = (m == 0u); g_scan_ctr = 0; }
    }
    int i = blockIdx.x * blockDim.x + threadIdx.x;
    if (i < M) g_deg[i] = 0;
}

__device__ __forceinline__ int edge_at(const int* ei32, int is64, long long idx) {
    return is64 ? ei32[2 * idx] : ei32[idx];   // little-endian low word
}

// ---------------------------------------------------------------------------
// Packed f32x2 helpers (sm_100+ PTX; ptxas never auto-fuses FFMA2)
// ---------------------------------------------------------------------------
__device__ __forceinline__ unsigned long long pack_dup(float x) {
    unsigned long long r;
    unsigned u = __float_as_uint(x);
    asm("mov.b64 %0, {%1, %1};" : "=l"(r) : "r"(u));
    return r;
}
__device__ __forceinline__ void fma_f32x2(unsigned long long& acc,
                                          unsigned long long a,
                                          unsigned long long b) {
    asm("fma.rn.f32x2 %0, %1, %2, %0;" : "+l"(acc) : "l"(a), "l"(b));
}

// ---------------------------------------------------------------------------
// GEMM (R7 form, pure): 128x64 tile, f32x2, 8x4 thread tile, fused s1/s2.
// Runs CONCURRENTLY with the rank->scan->scatter branch (separate stream).
// ---------------------------------------------------------------------------
__global__ __launch_bounds__(256) void gemm_kernel(
    const float* __restrict__ X, const float* __restrict__ W,
    const float* __restrict__ a, int M)
{
    __shared__ __align__(16) float Xs[32][132];
    __shared__ __align__(16) float Ws[32][64];

    int tid = threadIdx.x;
    int tx = tid & 15;   // col group: cols tx*4 .. tx*4+3
    int ty = tid >> 4;   // row group: rows ty*8 .. ty*8+7
    int m0 = blockIdx.x * 128;

    unsigned long long accp[4][4];
#pragma unroll
    for (int p = 0; p < 4; p++)
#pragma unroll
        for (int j = 0; j < 4; j++) accp[p][j] = 0ull;

    for (int k0 = 0; k0 < F_IN; k0 += 32) {
#pragma unroll
        for (int i = 0; i < 4; i++) {
            int idx = tid + i * 256;
            int r   = idx >> 3;
            int kc  = idx & 7;
            float4 v = make_float4(0.f, 0.f, 0.f, 0.f);
            int row = m0 + r;
            if (row < M)
                v = *(const float4*)(X + (size_t)row * F_IN + k0 + kc * 4);
            Xs[kc * 4 + 0][r] = v.x;
            Xs[kc * 4 + 1][r] = v.y;
            Xs[kc * 4 + 2][r] = v.z;
            Xs[kc * 4 + 3][r] = v.w;
        }
#pragma unroll
        for (int i = 0; i < 2; i++) {
            int idx = tid + i * 256;
            int kr  = idx >> 4;
            int c4  = idx & 15;
            float4 w = *(const float4*)(W + (size_t)(k0 + kr) * F_OUT + c4 * 4);
            *(float4*)&Ws[kr][c4 * 4] = w;
        }
        __syncthreads();

#pragma unroll
        for (int kk = 0; kk < 32; kk++) {
            float4 b = *(const float4*)&Ws[kk][tx * 4];
            unsigned long long bv0 = pack_dup(b.x);
            unsigned long long bv1 = pack_dup(b.y);
            unsigned long long bv2 = pack_dup(b.z);
            unsigned long long bv3 = pack_dup(b.w);
            unsigned long long av[4];
#pragma unroll
            for (int p = 0; p < 4; p++)
                av[p] = *(const unsigned long long*)&Xs[kk][ty * 8 + 2 * p];
#pragma unroll
            for (int p = 0; p < 4; p++) {
                fma_f32x2(accp[p][0], av[p], bv0);
                fma_f32x2(accp[p][1], av[p], bv1);
                fma_f32x2(accp[p][2], av[p], bv2);
                fma_f32x2(accp[p][3], av[p], bv3);
            }
        }
        __syncthreads();
    }

    float accf[8][4];
#pragma unroll
    for (int p = 0; p < 4; p++)
#pragma unroll
        for (int j = 0; j < 4; j++) {
            float2 f = *reinterpret_cast<float2*>(&accp[p][j]);
            accf[2 * p][j]     = f.x;
            accf[2 * p + 1][j] = f.y;
        }

    // Store h as fp16
#pragma unroll
    for (int i = 0; i < 8; i++) {
        int row = m0 + ty * 8 + i;
        if (row < M) {
            __half2 lo = __floats2half2_rn(accf[i][0], accf[i][1]);
            __half2 hi = __floats2half2_rn(accf[i][2], accf[i][3]);
            uint2 pkt = make_uint2(*(unsigned*)&lo, *(unsigned*)&hi);
            *(uint2*)(g_h16 + (size_t)row * F_OUT + tx * 4) = pkt;
        }
    }

    // Fused s1/s2 epilogue (fp32, exact)
    float a1v[4], a2v[4];
#pragma unroll
    for (int j = 0; j < 4; j++) {
        a1v[j] = __ldg(a + tx * 4 + j);
        a2v[j] = __ldg(a + 64 + tx * 4 + j);
    }
    float s1p[8], s2p[8];
#pragma unroll
    for (int i = 0; i < 8; i++) {
        float t1 = 0.f, t2 = 0.f;
#pragma unroll
        for (int j = 0; j < 4; j++) {
            t1 = fmaf(accf[i][j], a1v[j], t1);
            t2 = fmaf(accf[i][j], a2v[j], t2);
        }
        s1p[i] = t1; s2p[i] = t2;
    }
#pragma unroll
    for (int o = 1; o < 16; o <<= 1) {
#pragma unroll
        for (int i = 0; i < 8; i++) {
            s1p[i] += __shfl_xor_sync(0xffffffffu, s1p[i], o);
            s2p[i] += __shfl_xor_sync(0xffffffffu, s2p[i], o);
        }
    }
    if (tx == 0) {
#pragma unroll
        for (int i = 0; i < 8; i++) {
            int row = m0 + ty * 8 + i;
            if (row < M) { g_s1[row] = s1p[i]; g_s2[row] = s2p[i]; }
        }
    }
}

// ---------------------------------------------------------------------------
// rank pass: per-edge position within its src bucket (one atomic pass)
// ---------------------------------------------------------------------------
__global__ void rank_kernel(const int* __restrict__ ei32, int E, int M) {
    int e = blockIdx.x * blockDim.x + threadIdx.x;
    if (e >= E) return;
    int is64 = g_is64;
    int src = edge_at(ei32, is64, e);
    int dst = edge_at(ei32, is64, (long long)E + e);
    int r = -1;
    if ((unsigned)src < (unsigned)M && (unsigned)dst < (unsigned)M)
        r = atomicAdd(&g_deg[src], 1);
    g_rank[e] = r;
}

// ---------------------------------------------------------------------------
// Fused scan: per-1024-block local inclusive scan; the LAST block to finish
// also exclusive-scans the (<=128) block sums in place (threadfence+counter).
// ---------------------------------------------------------------------------
__global__ void scan_kernel(int n, int nblk) {
    __shared__ int s[1024];
    __shared__ int isLast;
    int i = blockIdx.x * 1024 + threadIdx.x;
    int v = (i < n) ? g_deg[i] : 0;
    s[threadIdx.x] = v;
    __syncthreads();
#pragma unroll
    for (int o = 1; o < 1024; o <<= 1) {
        int t = (threadIdx.x >= o) ? s[threadIdx.x - o] : 0;
        __syncthreads();
        s[threadIdx.x] += t;
        __syncthreads();
    }
    if (i < n) g_rowptr[i + 1] = s[threadIdx.x];
    if (threadIdx.x == 1023) {
        g_bsum[blockIdx.x] = s[1023];
        __threadfence();
        int prev = atomicAdd(&g_scan_ctr, 1);
        isLast = (prev == nblk - 1);
    }
    __syncthreads();
    if (isLast) {
        __threadfence();   // acquire all blocks' bsum writes
        int bv = (threadIdx.x < nblk) ? g_bsum[threadIdx.x] : 0;
        if (threadIdx.x < 128) s[threadIdx.x] = bv;
        __syncthreads();
#pragma unroll
        for (int o = 1; o < 128; o <<= 1) {
            int t = (threadIdx.x < 128 && threadIdx.x >= o) ? s[threadIdx.x - o] : 0;
            __syncthreads();
            if (threadIdx.x < 128) s[threadIdx.x] += t;
            __syncthreads();
        }
        if (threadIdx.x < nblk) g_bsum[threadIdx.x] = s[threadIdx.x] - bv;
    }
}

// ---------------------------------------------------------------------------
// Scatter: atomic-free using precomputed ranks; rowptr via rowbase() inline
// ---------------------------------------------------------------------------
__global__ void scatter_kernel(const int* __restrict__ ei32, int E, int M) {
    int e = blockIdx.x * blockDim.x + threadIdx.x;
    if (e >= E) return;
    int r = g_rank[e];
    if (r < 0) return;
    int is64 = g_is64;
    int src = edge_at(ei32, is64, e);
    int dst = edge_at(ei32, is64, (long long)E + e);
    g_sdst[rowbase(src) + r] = dst;
}

// ---------------------------------------------------------------------------
// Aggregate + finalize (R7 form, frozen): one warp per node, 4 edge-groups x
// 8 lanes x 8 feats, prefetch next sdst. Fused rowsum-divide + ELU.
// w = exp(lrelu(s1[src]+s2[dst]))   (global-max subtraction cancels; skipped)
// ---------------------------------------------------------------------------
__global__ void aggregate_kernel(float* __restrict__ out, int M) {
    int node = (blockIdx.x * blockDim.x + threadIdx.x) >> 5;
    if (node >= M) return;
    int lane = threadIdx.x & 31;
    int sub  = lane & 7;
    int eg   = lane >> 3;

    int beg = rowbase(node);
    int end = rowbase(node + 1);
    float s1v = g_s1[node];

    float acc[8];
#pragma unroll
    for (int j = 0; j < 8; j++) acc[j] = 0.0f;
    float wsum = 0.0f;

    int p = beg + eg;
    int dst_cur = (p < end) ? g_sdst[p] : 0;
    for (; p < end; p += 4) {
        int pn = p + 4;
        int dst_next = (pn < end) ? g_sdst[pn] : 0;   // prefetch

        float s2v = g_s2[dst_cur];
        uint4 q = *(const uint4*)(g_h16 + (size_t)dst_cur * F_OUT + sub * 8);

        float v  = s1v + s2v;
        float ev = v > 0.0f ? v : 0.2f * v;
        float w  = __expf(ev);
        wsum += w;

        float2 f0 = __half22float2(*(const __half2*)&q.x);
        float2 f1 = __half22float2(*(const __half2*)&q.y);
        float2 f2 = __half22float2(*(const __half2*)&q.z);
        float2 f3 = __half22float2(*(const __half2*)&q.w);
        acc[0] = fmaf(w, f0.x, acc[0]);
        acc[1] = fmaf(w, f0.y, acc[1]);
        acc[2] = fmaf(w, f1.x, acc[2]);
        acc[3] = fmaf(w, f1.y, acc[3]);
        acc[4] = fmaf(w, f2.x, acc[4]);
        acc[5] = fmaf(w, f2.y, acc[5]);
        acc[6] = fmaf(w, f3.x, acc[6]);
        acc[7] = fmaf(w, f3.y, acc[7]);

        dst_cur = dst_next;
    }

#pragma unroll
    for (int j = 0; j < 8; j++) {
        acc[j] += __shfl_xor_sync(0xffffffffu, acc[j], 8);
        acc[j] += __shfl_xor_sync(0xffffffffu, acc[j], 16);
    }
    wsum += __shfl_xor_sync(0xffffffffu, wsum, 8);
    wsum += __shfl_xor_sync(0xffffffffu, wsum, 16);

    if (eg == 0) {
        float inv = 1.0f / (wsum + 1e-15f);
        float o[8];
#pragma unroll
        for (int j = 0; j < 8; j++) {
            float hp = acc[j] * inv;
            o[j] = hp > 0.0f ? hp : expm1f(hp);
        }
        float* dst = out + (size_t)node * F_OUT + sub * 8;
        *(float4*)(dst)     = make_float4(o[0], o[1], o[2], o[3]);
        *(float4*)(dst + 4) = make_float4(o[4], o[5], o[6], o[7]);
    }
}

// ---------------------------------------------------------------------------
extern "C" void kernel_launch(void* const* d_in, const int* in_sizes, int n_in,
                              void* d_out, int out_size) {
    // Identify inputs by element count (robust to metadata ordering)
    int idx[4] = {0, 1, 2, 3};
    for (int i = 1; i < 4 && i < n_in; i++) {
        int k = idx[i], j = i - 1;
        while (j >= 0 && in_sizes[idx[j]] < in_sizes[k]) { idx[j + 1] = idx[j]; j--; }
        idx[j + 1] = k;
    }
    const float* X    = (const float*)d_in[idx[0]];
    const int*   ei32 = (const int*)d_in[idx[1]];
    const float* W    = (const float*)d_in[idx[2]];
    const float* a    = (const float*)d_in[idx[3]];
    float*       out  = (float*)d_out;

    int M = in_sizes[idx[0]] / F_IN;   // 100000
    int E = in_sizes[idx[1]] / 2;      // 3200000

    // Fork-join graph: branch A (default stream) = gemm;
    // branch B (s2) = rank -> scan -> scatter. Join before aggregate.
    // Host objects are created/destroyed only during capture; replays run
    // the recorded graph with true parallel branches.
    cudaStream_t s2;
    cudaStreamCreateWithFlags(&s2, cudaStreamNonBlocking);
    cudaEvent_t evFork, evJoin;
    cudaEventCreateWithFlags(&evFork, cudaEventDisableTiming);
    cudaEventCreateWithFlags(&evJoin, cudaEventDisableTiming);

    init_kernel<<<(M + 511) / 512, 512>>>(ei32, M);
    cudaEventRecord(evFork, 0);
    cudaStreamWaitEvent(s2, evFork, 0);

    // Branch B on s2: edge pipeline (independent of gemm outputs)
    rank_kernel<<<(E + 255) / 256, 256, 0, s2>>>(ei32, E, M);
    int nblk = (M + 1023) / 1024;
    scan_kernel<<<nblk, 1024, 0, s2>>>(M, nblk);
    scatter_kernel<<<(E + 255) / 256, 256, 0, s2>>>(ei32, E, M);
    cudaEventRecord(evJoin, s2);

    // Branch A on default stream: gemm + fused s1/s2
    gemm_kernel<<<(M + 127) / 128, 256>>>(X, W, a, M);

    // Join, then aggregate
    cudaStreamWaitEvent(0, evJoin, 0);
    aggregate_kernel<<<(M * 32 + 255) / 256, 256>>>(out, M);

    cudaEventDestroy(evFork);
    cudaEventDestroy(evJoin);
    cudaStreamDestroy(s2);
}